// round 9
// baseline (speedup 1.0000x reference)
#include <cuda_runtime.h>

// Problem constants
#define NB 4
#define TT 2048
#define DD 512
#define HH 8
#define HDIM 64
#define MROWS (NB * TT)   // 8192

// Scratch (allocation-free: __device__ globals)
__device__ float g_keys[NB * TT * DD];   // tf32-RNE-rounded
__device__ float g_vals[NB * TT * DD];   // tf32-RNE-rounded
__device__ float g_attn[NB * TT * DD];   // tf32-RNE-rounded (flash epilogue)
__device__ float g_qtf [NB * TT * DD];   // tf32-RNE-rounded q
__device__ float g_wk  [DD * DD];        // tf32-RNE-rounded weights
__device__ float g_wv  [DD * DD];
__device__ float g_wo  [DD * DD];

// ---------------------------------------------------------------------------
// fp32 -> tf32 helpers + m16n8k8 tf32 mma (fp32 accumulate) + cp.async
// ---------------------------------------------------------------------------
__device__ __forceinline__ unsigned f2tf(float x) {
    unsigned r;
    asm("cvt.rna.tf32.f32 %0, %1;" : "=r"(r) : "f"(x));
    return r;
}
__device__ __forceinline__ float f2tf_f(float x) { return __uint_as_float(f2tf(x)); }

__device__ __forceinline__ void mma_tf32(float& c0, float& c1, float& c2, float& c3,
                                         unsigned a0, unsigned a1, unsigned a2, unsigned a3,
                                         unsigned b0, unsigned b1) {
    asm volatile(
        "mma.sync.aligned.m16n8k8.row.col.f32.tf32.tf32.f32 "
        "{%0,%1,%2,%3}, {%4,%5,%6,%7}, {%8,%9}, {%0,%1,%2,%3};"
        : "+f"(c0), "+f"(c1), "+f"(c2), "+f"(c3)
        : "r"(a0), "r"(a1), "r"(a2), "r"(a3), "r"(b0), "r"(b1));
}

__device__ __forceinline__ void cp_async16(unsigned saddr, const void* gptr) {
    asm volatile("cp.async.cg.shared.global [%0], [%1], 16;" :: "r"(saddr), "l"(gptr));
}

// ---------------------------------------------------------------------------
// Prep: elementwise tf32-RNE rounding pass (vectorized)
// ---------------------------------------------------------------------------
__global__ void round_tf32(const float* __restrict__ src, float* __restrict__ dst, int n4) {
    int i = blockIdx.x * blockDim.x + threadIdx.x;
    if (i < n4) {
        float4 v = ((const float4*)src)[i];
        ((float4*)dst)[i] =
            make_float4(f2tf_f(v.x), f2tf_f(v.y), f2tf_f(v.z), f2tf_f(v.w));
    }
}

// ---------------------------------------------------------------------------
// Tensor-core GEMM NT, cp.async double-buffered (inputs pre-rounded to tf32):
// C[M,512] = A @ B^T (+ optional fp32 residual R). BM=BN=128, BK=32.
// 256 threads = 8 warps (4M x 2N), warp tile 32x64. GSTR=36 (144B rows: 16B-mult).
// ---------------------------------------------------------------------------
#define GSTR 36
#define GEMM_STAGE_FLOATS (128 * GSTR)
#define GEMM_SMEM_BYTES (4 * GEMM_STAGE_FLOATS * 4)   // 2 stages x (A+B)

template <bool RESIDUAL, bool TF32OUT>
__global__ __launch_bounds__(256, 2) void tgemm_db(const float* __restrict__ A,
                                                   const float* __restrict__ B,
                                                   const float* __restrict__ R,
                                                   float* __restrict__ C) {
    constexpr int BM = 128, BK = 32, NKT_G = DD / BK;   // 16
    extern __shared__ float gsm[];
    float* Asm[2] = {gsm, gsm + 2 * GEMM_STAGE_FLOATS};
    float* Bsm[2] = {gsm + GEMM_STAGE_FLOATS, gsm + 3 * GEMM_STAGE_FLOATS};
    unsigned asmu[2], bsmu[2];
#pragma unroll
    for (int s = 0; s < 2; s++) {
        asmu[s] = (unsigned)__cvta_generic_to_shared(Asm[s]);
        bsmu[s] = (unsigned)__cvta_generic_to_shared(Bsm[s]);
    }

    const int tid  = threadIdx.x;
    const int lane = tid & 31;
    const int wid  = tid >> 5;
    const int l4   = lane & 3;
    const int g    = lane >> 2;
    const int wm   = (wid & 3) * 32;
    const int wn   = (wid >> 2) * 64;
    const int bm   = blockIdx.x * BM;
    const int bn   = blockIdx.y * BM;

    const int lr  = tid >> 3;          // 0..31... (for loads) r = i>>3 below
    (void)lr;

    float c[2][8][4];
#pragma unroll
    for (int mt = 0; mt < 2; mt++)
#pragma unroll
        for (int nt = 0; nt < 8; nt++)
#pragma unroll
            for (int j = 0; j < 4; j++) c[mt][nt][j] = 0.f;

    // issue one K-tile's loads into stage s
    auto issue = [&](int kt, int s) {
        int k0 = kt * BK;
#pragma unroll
        for (int it = 0; it < 4; it++) {
            int i  = tid + it * 256;       // 0..1023
            int r  = i >> 3;               // 0..127
            int c4 = (i & 7) << 2;         // 0..28
            unsigned off = (unsigned)(r * GSTR + c4) * 4u;
            cp_async16(asmu[s] + off, A + (size_t)(bm + r) * DD + k0 + c4);
            cp_async16(bsmu[s] + off, B + (size_t)(bn + r) * DD + k0 + c4);
        }
        asm volatile("cp.async.commit_group;");
    };

    issue(0, 0);

    for (int kt = 0; kt < NKT_G; kt++) {
        const int s = kt & 1;
        if (kt + 1 < NKT_G) {
            issue(kt + 1, s ^ 1);
            asm volatile("cp.async.wait_group 1;");
        } else {
            asm volatile("cp.async.wait_group 0;");
        }
        __syncthreads();

        const float* As = Asm[s];
        const float* Bs = Bsm[s];
#pragma unroll
        for (int k8 = 0; k8 < BK / 8; k8++) {
            unsigned a[2][4];
#pragma unroll
            for (int mt = 0; mt < 2; mt++) {
                int base = (wm + mt * 16 + g) * GSTR + k8 * 8 + l4;
                a[mt][0] = __float_as_uint(As[base]);
                a[mt][1] = __float_as_uint(As[base + 8 * GSTR]);
                a[mt][2] = __float_as_uint(As[base + 4]);
                a[mt][3] = __float_as_uint(As[base + 8 * GSTR + 4]);
            }
#pragma unroll
            for (int nt = 0; nt < 8; nt++) {
                int bb = (wn + nt * 8 + g) * GSTR + k8 * 8 + l4;
                unsigned b0 = __float_as_uint(Bs[bb]);
                unsigned b1 = __float_as_uint(Bs[bb + 4]);
                mma_tf32(c[0][nt][0], c[0][nt][1], c[0][nt][2], c[0][nt][3],
                         a[0][0], a[0][1], a[0][2], a[0][3], b0, b1);
                mma_tf32(c[1][nt][0], c[1][nt][1], c[1][nt][2], c[1][nt][3],
                         a[1][0], a[1][1], a[1][2], a[1][3], b0, b1);
            }
        }
        __syncthreads();   // stage consumed by all warps before next overwrite
    }

#pragma unroll
    for (int mt = 0; mt < 2; mt++) {
        int r1 = bm + wm + mt * 16 + g;
        int r2 = r1 + 8;
#pragma unroll
        for (int nt = 0; nt < 8; nt++) {
            int col = bn + wn + nt * 8 + 2 * l4;
            float2 v1 = make_float2(c[mt][nt][0], c[mt][nt][1]);
            float2 v2 = make_float2(c[mt][nt][2], c[mt][nt][3]);
            if (RESIDUAL) {
                float2 q1 = *(const float2*)(R + (size_t)r1 * DD + col);
                float2 q2 = *(const float2*)(R + (size_t)r2 * DD + col);
                v1.x += q1.x; v1.y += q1.y;
                v2.x += q2.x; v2.y += q2.y;
            }
            if (TF32OUT) {
                v1.x = f2tf_f(v1.x); v1.y = f2tf_f(v1.y);
                v2.x = f2tf_f(v2.x); v2.y = f2tf_f(v2.y);
            }
            *(float2*)(C + (size_t)r1 * DD + col) = v1;
            *(float2*)(C + (size_t)r2 * DD + col) = v2;
        }
    }
}

// ---------------------------------------------------------------------------
// Flash attention on tensor cores (tf32 mma, fp32 accumulate). (proven R8)
// Epilogue now rounds output to tf32 (consumed raw by the Wo GEMM).
// ---------------------------------------------------------------------------
#define BQ 128
#define BKV 64
#define FSTR 68
#define NKT (TT / BKV)

#define FLASH_SMEM_FLOATS (FSTR * (BQ + 4 * BKV))
#define FLASH_SMEM_BYTES (FLASH_SMEM_FLOATS * 4)

__global__ __launch_bounds__(256, 2) void flash_attn_tc(const float* __restrict__ Q) {
    extern __shared__ float sm[];
    float* Qp  = sm;
    float* Ks0 = Qp  + BQ  * FSTR;
    float* Ks1 = Ks0 + BKV * FSTR;
    float* Vs0 = Ks1 + BKV * FSTR;
    float* Vs1 = Vs0 + BKV * FSTR;

    const unsigned ks0u = (unsigned)__cvta_generic_to_shared(Ks0);
    const unsigned ks1u = (unsigned)__cvta_generic_to_shared(Ks1);
    const unsigned vs0u = (unsigned)__cvta_generic_to_shared(Vs0);
    const unsigned vs1u = (unsigned)__cvta_generic_to_shared(Vs1);

    const int tid  = threadIdx.x;
    const int lane = tid & 31;
    const int wid  = tid >> 5;
    const int l4   = lane & 3;
    const int g    = lane >> 2;
    const int wb   = wid * 16;

    const int qt = blockIdx.x;
    const int nh = blockIdx.y;
    const int n  = nh >> 3;
    const int h  = nh & 7;

    const float* Qbase = Q      + (size_t)n * TT * DD + (size_t)(qt * BQ) * DD + h * HDIM;
    const float* Kbase = g_keys + (size_t)n * TT * DD + h * HDIM;
    const float* Vbase = g_vals + (size_t)n * TT * DD + h * HDIM;

    const float QSCALE = 0.125f * 1.44269504088896341f;
    for (int i = tid; i < BQ * 16; i += 256) {
        int r = i >> 4, d4 = (i & 15) << 2;
        float4 v = *(const float4*)(Qbase + (size_t)r * DD + d4);
        *(float4*)&Qp[r * FSTR + d4] =
            make_float4(f2tf_f(v.x * QSCALE), f2tf_f(v.y * QSCALE),
                        f2tf_f(v.z * QSCALE), f2tf_f(v.w * QSCALE));
    }

#pragma unroll
    for (int it = 0; it < 4; it++) {
        int i = tid + it * 256;
        int tok = i >> 4, d4 = (i & 15) << 2;
        unsigned off = (unsigned)(tok * FSTR + d4) * 4u;
        cp_async16(ks0u + off, Kbase + (size_t)tok * DD + d4);
        cp_async16(vs0u + off, Vbase + (size_t)tok * DD + d4);
    }
    asm volatile("cp.async.commit_group;");

    __syncthreads();

    unsigned qf[8][4];
#pragma unroll
    for (int k = 0; k < 8; k++) {
        int qa = (wb + g) * FSTR + k * 8 + l4;
        qf[k][0] = __float_as_uint(Qp[qa]);
        qf[k][1] = __float_as_uint(Qp[qa + 8 * FSTR]);
        qf[k][2] = __float_as_uint(Qp[qa + 4]);
        qf[k][3] = __float_as_uint(Qp[qa + 8 * FSTR + 4]);
    }

    float m1 = -1e30f, m2 = -1e30f, l1 = 0.f, l2 = 0.f;
    float oc[8][4];
#pragma unroll
    for (int nt = 0; nt < 8; nt++)
#pragma unroll
        for (int j = 0; j < 4; j++) oc[nt][j] = 0.f;

    for (int kt = 0; kt < NKT; kt++) {
        const bool odd = kt & 1;
        float* Kc = odd ? Ks1 : Ks0;
        float* Vc = odd ? Vs1 : Vs0;

        if (kt + 1 < NKT) {
            unsigned knu = odd ? ks0u : ks1u;
            unsigned vnu = odd ? vs0u : vs1u;
            const float* Kt = Kbase + (size_t)((kt + 1) * BKV) * DD;
            const float* Vt = Vbase + (size_t)((kt + 1) * BKV) * DD;
#pragma unroll
            for (int it = 0; it < 4; it++) {
                int i = tid + it * 256;
                int tok = i >> 4, d4 = (i & 15) << 2;
                unsigned off = (unsigned)(tok * FSTR + d4) * 4u;
                cp_async16(knu + off, Kt + (size_t)tok * DD + d4);
                cp_async16(vnu + off, Vt + (size_t)tok * DD + d4);
            }
            asm volatile("cp.async.commit_group;");
            asm volatile("cp.async.wait_group 1;");
        } else {
            asm volatile("cp.async.wait_group 0;");
        }
        __syncthreads();

        float sc[8][4];
#pragma unroll
        for (int nt = 0; nt < 8; nt++)
#pragma unroll
            for (int j = 0; j < 4; j++) sc[nt][j] = 0.f;

#pragma unroll
        for (int k = 0; k < 8; k++) {
#pragma unroll
            for (int nt = 0; nt < 8; nt++) {
                int kb = (nt * 8 + g) * FSTR + k * 8 + l4;
                unsigned b0 = __float_as_uint(Kc[kb]);
                unsigned b1 = __float_as_uint(Kc[kb + 4]);
                mma_tf32(sc[nt][0], sc[nt][1], sc[nt][2], sc[nt][3],
                         qf[k][0], qf[k][1], qf[k][2], qf[k][3], b0, b1);
            }
        }

        float rmax1 = -1e30f, rmax2 = -1e30f;
#pragma unroll
        for (int nt = 0; nt < 8; nt++) {
            rmax1 = fmaxf(rmax1, fmaxf(sc[nt][0], sc[nt][1]));
            rmax2 = fmaxf(rmax2, fmaxf(sc[nt][2], sc[nt][3]));
        }
        rmax1 = fmaxf(rmax1, __shfl_xor_sync(0xffffffffu, rmax1, 1, 4));
        rmax1 = fmaxf(rmax1, __shfl_xor_sync(0xffffffffu, rmax1, 2, 4));
        rmax2 = fmaxf(rmax2, __shfl_xor_sync(0xffffffffu, rmax2, 1, 4));
        rmax2 = fmaxf(rmax2, __shfl_xor_sync(0xffffffffu, rmax2, 2, 4));

        float mn1 = fmaxf(m1, rmax1), mn2 = fmaxf(m2, rmax2);
        float corr1 = exp2f(m1 - mn1), corr2 = exp2f(m2 - mn2);

        float sum1 = 0.f, sum2 = 0.f;
#pragma unroll
        for (int nt = 0; nt < 8; nt++) {
            float p0 = exp2f(sc[nt][0] - mn1);
            float p1 = exp2f(sc[nt][1] - mn1);
            float p2 = exp2f(sc[nt][2] - mn2);
            float p3 = exp2f(sc[nt][3] - mn2);
            sum1 += p0 + p1;
            sum2 += p2 + p3;
            *(float2*)&Qp[(wb + g) * FSTR + nt * 8 + 2 * l4] =
                make_float2(f2tf_f(p0), f2tf_f(p1));
            *(float2*)&Qp[(wb + g + 8) * FSTR + nt * 8 + 2 * l4] =
                make_float2(f2tf_f(p2), f2tf_f(p3));
        }
        sum1 += __shfl_xor_sync(0xffffffffu, sum1, 1, 4);
        sum1 += __shfl_xor_sync(0xffffffffu, sum1, 2, 4);
        sum2 += __shfl_xor_sync(0xffffffffu, sum2, 1, 4);
        sum2 += __shfl_xor_sync(0xffffffffu, sum2, 2, 4);

        l1 = l1 * corr1 + sum1;  m1 = mn1;
        l2 = l2 * corr2 + sum2;  m2 = mn2;
#pragma unroll
        for (int nt = 0; nt < 8; nt++) {
            oc[nt][0] *= corr1; oc[nt][1] *= corr1;
            oc[nt][2] *= corr2; oc[nt][3] *= corr2;
        }

        __syncwarp();

#pragma unroll
        for (int k = 0; k < 8; k++) {
            int pa = (wb + g) * FSTR + k * 8 + l4;
            unsigned a0 = __float_as_uint(Qp[pa]);
            unsigned a1 = __float_as_uint(Qp[pa + 8 * FSTR]);
            unsigned a2 = __float_as_uint(Qp[pa + 4]);
            unsigned a3 = __float_as_uint(Qp[pa + 8 * FSTR + 4]);
#pragma unroll
            for (int nt = 0; nt < 8; nt++) {
                unsigned b0 = __float_as_uint(Vc[(k * 8 + l4) * FSTR + nt * 8 + g]);
                unsigned b1 = __float_as_uint(Vc[(k * 8 + l4 + 4) * FSTR + nt * 8 + g]);
                mma_tf32(oc[nt][0], oc[nt][1], oc[nt][2], oc[nt][3],
                         a0, a1, a2, a3, b0, b1);
            }
        }
        __syncthreads();
    }

    float inv1 = 1.0f / l1, inv2 = 1.0f / l2;
    float* Ob = g_attn + (size_t)n * TT * DD + (size_t)(qt * BQ) * DD + h * HDIM;
#pragma unroll
    for (int nt = 0; nt < 8; nt++) {
        *(float2*)&Ob[(size_t)(wb + g) * DD + nt * 8 + 2 * l4] =
            make_float2(f2tf_f(oc[nt][0] * inv1), f2tf_f(oc[nt][1] * inv1));
        *(float2*)&Ob[(size_t)(wb + g + 8) * DD + nt * 8 + 2 * l4] =
            make_float2(f2tf_f(oc[nt][2] * inv2), f2tf_f(oc[nt][3] * inv2));
    }
}

// ---------------------------------------------------------------------------
// Launch
// ---------------------------------------------------------------------------
extern "C" void kernel_launch(void* const* d_in, const int* in_sizes, int n_in,
                              void* d_out, int out_size) {
    const float* q  = (const float*)d_in[0];
    const float* Wk = (const float*)d_in[1];
    const float* Wv = (const float*)d_in[2];
    const float* Wo = (const float*)d_in[3];
    float* out = (float*)d_out;

    float *keys, *vals, *attn, *qtf, *wk, *wv, *wo;
    cudaGetSymbolAddress((void**)&keys, g_keys);
    cudaGetSymbolAddress((void**)&vals, g_vals);
    cudaGetSymbolAddress((void**)&attn, g_attn);
    cudaGetSymbolAddress((void**)&qtf,  g_qtf);
    cudaGetSymbolAddress((void**)&wk,   g_wk);
    cudaGetSymbolAddress((void**)&wv,   g_wv);
    cudaGetSymbolAddress((void**)&wo,   g_wo);

    // Pre-round inputs to tf32 (RNE) so GEMMs can cp.async raw bytes.
    const int nq4 = MROWS * DD / 4;      // 1,048,576
    const int nw4 = DD * DD / 4;         // 65,536
    round_tf32<<<(nq4 + 255) / 256, 256>>>(q,  qtf, nq4);
    round_tf32<<<(nw4 + 255) / 256, 256>>>(Wk, wk,  nw4);
    round_tf32<<<(nw4 + 255) / 256, 256>>>(Wv, wv,  nw4);
    round_tf32<<<(nw4 + 255) / 256, 256>>>(Wo, wo,  nw4);

    dim3 gGemm(MROWS / 128, DD / 128);   // (64, 4)
    cudaFuncSetAttribute(tgemm_db<true , true >, cudaFuncAttributeMaxDynamicSharedMemorySize, GEMM_SMEM_BYTES);
    cudaFuncSetAttribute(tgemm_db<false, true >, cudaFuncAttributeMaxDynamicSharedMemorySize, GEMM_SMEM_BYTES);
    cudaFuncSetAttribute(tgemm_db<false, false>, cudaFuncAttributeMaxDynamicSharedMemorySize, GEMM_SMEM_BYTES);

    // keys = tf32(qtf @ wk^T + q) ; vals = tf32(qtf @ wv^T)
    tgemm_db<true , true ><<<gGemm, 256, GEMM_SMEM_BYTES>>>(qtf, wk, q, keys);
    tgemm_db<false, true ><<<gGemm, 256, GEMM_SMEM_BYTES>>>(qtf, wv, nullptr, vals);

    // flash attention (tf32, cp.async double-buffered)
    cudaFuncSetAttribute(flash_attn_tc, cudaFuncAttributeMaxDynamicSharedMemorySize,
                         FLASH_SMEM_BYTES);
    dim3 gFlash(TT / BQ, NB * HH);       // (16, 32)
    flash_attn_tc<<<gFlash, 256, FLASH_SMEM_BYTES>>>(q);

    // out = attn @ wo^T (fp32 output)
    tgemm_db<false, false><<<gGemm, 256, GEMM_SMEM_BYTES>>>(attn, wo, nullptr, out);
}

// round 12
// speedup vs baseline: 1.0431x; 1.0431x over previous
#include <cuda_runtime.h>

// Problem constants
#define NB 4
#define TT 2048
#define DD 512
#define HH 8
#define HDIM 64
#define MROWS (NB * TT)   // 8192

// Scratch (allocation-free: __device__ globals)
__device__ float g_keys[NB * TT * DD];   // stored tf32-RNE-rounded
__device__ float g_vals[NB * TT * DD];   // stored tf32-RNE-rounded
__device__ float g_attn[NB * TT * DD];

// ---------------------------------------------------------------------------
// fp32 -> tf32 helpers + m16n8k8 tf32 mma (fp32 accumulate) + cp.async + ex2
// ---------------------------------------------------------------------------
__device__ __forceinline__ unsigned f2tf(float x) {
    unsigned r;
    asm("cvt.rna.tf32.f32 %0, %1;" : "=r"(r) : "f"(x));
    return r;
}
__device__ __forceinline__ float f2tf_f(float x) { return __uint_as_float(f2tf(x)); }

__device__ __forceinline__ float ex2f(float x) {
    float y;
    asm("ex2.approx.ftz.f32 %0, %1;" : "=f"(y) : "f"(x));
    return y;
}

__device__ __forceinline__ void mma_tf32(float& c0, float& c1, float& c2, float& c3,
                                         unsigned a0, unsigned a1, unsigned a2, unsigned a3,
                                         unsigned b0, unsigned b1) {
    asm volatile(
        "mma.sync.aligned.m16n8k8.row.col.f32.tf32.tf32.f32 "
        "{%0,%1,%2,%3}, {%4,%5,%6,%7}, {%8,%9}, {%0,%1,%2,%3};"
        : "+f"(c0), "+f"(c1), "+f"(c2), "+f"(c3)
        : "r"(a0), "r"(a1), "r"(a2), "r"(a3), "r"(b0), "r"(b1));
}

__device__ __forceinline__ void cp_async16(unsigned saddr, const void* gptr) {
    asm volatile("cp.async.cg.shared.global [%0], [%1], 16;" :: "r"(saddr), "l"(gptr));
}

// ---------------------------------------------------------------------------
// Tensor-core GEMM NT (tf32): C[M,512] = A[M,512] @ B[512,512]^T (+ residual A)
// BM=BN=128, BK=32, 256 threads = 8 warps (4M x 2N). Proven R8: 44 us.
// TF32OUT: round stored result (keys/vals consumed raw by flash's cp.async).
// ---------------------------------------------------------------------------
#define GSTR 36

template <bool RESIDUAL, bool TF32OUT>
__global__ __launch_bounds__(256, 2) void tgemm_nt(const float* __restrict__ A,
                                                   const float* __restrict__ B,
                                                   float* __restrict__ C) {
    constexpr int BM = 128, BN = 128, BK = 32;
    __shared__ float Asm[BM * GSTR];
    __shared__ float Bsm[BN * GSTR];

    const int tid  = threadIdx.x;
    const int lane = tid & 31;
    const int wid  = tid >> 5;
    const int l4   = lane & 3;
    const int g    = lane >> 2;
    const int wm   = (wid & 3) * 32;
    const int wn   = (wid >> 2) * 64;
    const int bm   = blockIdx.x * BM;
    const int bn   = blockIdx.y * BN;

    float c[2][8][4];
#pragma unroll
    for (int mt = 0; mt < 2; mt++)
#pragma unroll
        for (int nt = 0; nt < 8; nt++)
#pragma unroll
            for (int j = 0; j < 4; j++) c[mt][nt][j] = 0.f;

    for (int k0 = 0; k0 < DD; k0 += BK) {
        __syncthreads();
#pragma unroll
        for (int it = 0; it < 4; it++) {
            int i  = tid + it * 256;
            int r  = i >> 3;
            int c4 = (i & 7) << 2;
            float4 va = *(const float4*)(A + (size_t)(bm + r) * DD + k0 + c4);
            *(float4*)&Asm[r * GSTR + c4] =
                make_float4(f2tf_f(va.x), f2tf_f(va.y), f2tf_f(va.z), f2tf_f(va.w));
            float4 vb = *(const float4*)(B + (size_t)(bn + r) * DD + k0 + c4);
            *(float4*)&Bsm[r * GSTR + c4] =
                make_float4(f2tf_f(vb.x), f2tf_f(vb.y), f2tf_f(vb.z), f2tf_f(vb.w));
        }
        __syncthreads();

#pragma unroll
        for (int k8 = 0; k8 < BK / 8; k8++) {
            unsigned a[2][4];
#pragma unroll
            for (int mt = 0; mt < 2; mt++) {
                int base = (wm + mt * 16 + g) * GSTR + k8 * 8 + l4;
                a[mt][0] = __float_as_uint(Asm[base]);
                a[mt][1] = __float_as_uint(Asm[base + 8 * GSTR]);
                a[mt][2] = __float_as_uint(Asm[base + 4]);
                a[mt][3] = __float_as_uint(Asm[base + 8 * GSTR + 4]);
            }
#pragma unroll
            for (int nt = 0; nt < 8; nt++) {
                int bb = (wn + nt * 8 + g) * GSTR + k8 * 8 + l4;
                unsigned b0 = __float_as_uint(Bsm[bb]);
                unsigned b1 = __float_as_uint(Bsm[bb + 4]);
                mma_tf32(c[0][nt][0], c[0][nt][1], c[0][nt][2], c[0][nt][3],
                         a[0][0], a[0][1], a[0][2], a[0][3], b0, b1);
                mma_tf32(c[1][nt][0], c[1][nt][1], c[1][nt][2], c[1][nt][3],
                         a[1][0], a[1][1], a[1][2], a[1][3], b0, b1);
            }
        }
    }

#pragma unroll
    for (int mt = 0; mt < 2; mt++) {
        int r1 = bm + wm + mt * 16 + g;
        int r2 = r1 + 8;
#pragma unroll
        for (int nt = 0; nt < 8; nt++) {
            int col = bn + wn + nt * 8 + 2 * l4;
            float2 v1 = make_float2(c[mt][nt][0], c[mt][nt][1]);
            float2 v2 = make_float2(c[mt][nt][2], c[mt][nt][3]);
            if (RESIDUAL) {
                float2 q1 = *(const float2*)(A + (size_t)r1 * DD + col);
                float2 q2 = *(const float2*)(A + (size_t)r2 * DD + col);
                v1.x += q1.x; v1.y += q1.y;
                v2.x += q2.x; v2.y += q2.y;
            }
            if (TF32OUT) {
                v1.x = f2tf_f(v1.x); v1.y = f2tf_f(v1.y);
                v2.x = f2tf_f(v2.x); v2.y = f2tf_f(v2.y);
            }
            *(float2*)(C + (size_t)r1 * DD + col) = v1;
            *(float2*)(C + (size_t)r2 * DD + col) = v2;
        }
    }
}

// ---------------------------------------------------------------------------
// Flash attention on tensor cores (tf32 mma, fp32 accumulate).
// Single __syncthreads per KV tile (wait -> sync -> issue-next -> compute)
// + MUFU ex2.approx for softmax exponentials.
// ---------------------------------------------------------------------------
#define BQ 128
#define BKV 64
#define FSTR 68
#define NKT (TT / BKV)   // 32 KV tiles

// Qp(=Ps)[128] Ks0[64] Ks1[64] Vs0[64] Vs1[64] rows of FSTR floats
#define FLASH_SMEM_FLOATS (FSTR * (BQ + 4 * BKV))
#define FLASH_SMEM_BYTES (FLASH_SMEM_FLOATS * 4)

__global__ __launch_bounds__(256, 2) void flash_attn_tc(const float* __restrict__ Q) {
    extern __shared__ float sm[];
    float* Qp  = sm;                      // Q staging, then P slab (warp-private rows)
    float* Ks0 = Qp  + BQ  * FSTR;
    float* Ks1 = Ks0 + BKV * FSTR;
    float* Vs0 = Ks1 + BKV * FSTR;
    float* Vs1 = Vs0 + BKV * FSTR;

    const unsigned ks0u = (unsigned)__cvta_generic_to_shared(Ks0);
    const unsigned ks1u = (unsigned)__cvta_generic_to_shared(Ks1);
    const unsigned vs0u = (unsigned)__cvta_generic_to_shared(Vs0);
    const unsigned vs1u = (unsigned)__cvta_generic_to_shared(Vs1);

    const int tid  = threadIdx.x;
    const int lane = tid & 31;
    const int wid  = tid >> 5;
    const int l4   = lane & 3;
    const int g    = lane >> 2;
    const int wb   = wid * 16;

    const int qt = blockIdx.x;
    const int nh = blockIdx.y;
    const int n  = nh >> 3;
    const int h  = nh & 7;

    const float* Qbase = Q      + (size_t)n * TT * DD + (size_t)(qt * BQ) * DD + h * HDIM;
    const float* Kbase = g_keys + (size_t)n * TT * DD + h * HDIM;
    const float* Vbase = g_vals + (size_t)n * TT * DD + h * HDIM;

    // Q tile: pre-scale by (1/sqrt(HD)) * log2(e) for exp2-domain softmax.
    const float QSCALE = 0.125f * 1.44269504088896341f;
    for (int i = tid; i < BQ * 16; i += 256) {
        int r = i >> 4, d4 = (i & 15) << 2;
        float4 v = *(const float4*)(Qbase + (size_t)r * DD + d4);
        *(float4*)&Qp[r * FSTR + d4] =
            make_float4(f2tf_f(v.x * QSCALE), f2tf_f(v.y * QSCALE),
                        f2tf_f(v.z * QSCALE), f2tf_f(v.w * QSCALE));
    }

    // Prologue: async-load KV tile 0 into buffer 0 (K/V already tf32 bits).
#pragma unroll
    for (int it = 0; it < 4; it++) {
        int i = tid + it * 256;
        int tok = i >> 4, d4 = (i & 15) << 2;
        unsigned off = (unsigned)(tok * FSTR + d4) * 4u;
        cp_async16(ks0u + off, Kbase + (size_t)tok * DD + d4);
        cp_async16(vs0u + off, Vbase + (size_t)tok * DD + d4);
    }
    asm volatile("cp.async.commit_group;");

    __syncthreads();   // Qp staging complete

    // Hoist Q fragments (loop-invariant).
    unsigned qf[8][4];
#pragma unroll
    for (int k = 0; k < 8; k++) {
        int qa = (wb + g) * FSTR + k * 8 + l4;
        qf[k][0] = __float_as_uint(Qp[qa]);
        qf[k][1] = __float_as_uint(Qp[qa + 8 * FSTR]);
        qf[k][2] = __float_as_uint(Qp[qa + 4]);
        qf[k][3] = __float_as_uint(Qp[qa + 8 * FSTR + 4]);
    }

    float m1 = -1e30f, m2 = -1e30f, l1 = 0.f, l2 = 0.f;
    float oc[8][4];
#pragma unroll
    for (int nt = 0; nt < 8; nt++)
#pragma unroll
        for (int j = 0; j < 4; j++) oc[nt][j] = 0.f;

    for (int kt = 0; kt < NKT; kt++) {
        const bool odd = kt & 1;
        float* Kc = odd ? Ks1 : Ks0;
        float* Vc = odd ? Vs1 : Vs0;

        // Tile kt's group is the only one pending (issued last iter / prologue).
        asm volatile("cp.async.wait_group 0;");
        __syncthreads();   // publishes tile kt; also proves buffer s^1 fully consumed

        if (kt + 1 < NKT) {
            // Prefetch tile kt+1 into the other buffer; overlaps with compute below.
            unsigned knu = odd ? ks0u : ks1u;
            unsigned vnu = odd ? vs0u : vs1u;
            const float* Kt = Kbase + (size_t)((kt + 1) * BKV) * DD;
            const float* Vt = Vbase + (size_t)((kt + 1) * BKV) * DD;
#pragma unroll
            for (int it = 0; it < 4; it++) {
                int i = tid + it * 256;
                int tok = i >> 4, d4 = (i & 15) << 2;
                unsigned off = (unsigned)(tok * FSTR + d4) * 4u;
                cp_async16(knu + off, Kt + (size_t)tok * DD + d4);
                cp_async16(vnu + off, Vt + (size_t)tok * DD + d4);
            }
            asm volatile("cp.async.commit_group;");
        }

        // ---- S = Q @ K^T
        float sc[8][4];
#pragma unroll
        for (int nt = 0; nt < 8; nt++)
#pragma unroll
            for (int j = 0; j < 4; j++) sc[nt][j] = 0.f;

#pragma unroll
        for (int k = 0; k < 8; k++) {
#pragma unroll
            for (int nt = 0; nt < 8; nt++) {
                int kb = (nt * 8 + g) * FSTR + k * 8 + l4;
                unsigned b0 = __float_as_uint(Kc[kb]);
                unsigned b1 = __float_as_uint(Kc[kb + 4]);
                mma_tf32(sc[nt][0], sc[nt][1], sc[nt][2], sc[nt][3],
                         qf[k][0], qf[k][1], qf[k][2], qf[k][3], b0, b1);
            }
        }

        // ---- Online softmax (exp2 domain, MUFU)
        float rmax1 = -1e30f, rmax2 = -1e30f;
#pragma unroll
        for (int nt = 0; nt < 8; nt++) {
            rmax1 = fmaxf(rmax1, fmaxf(sc[nt][0], sc[nt][1]));
            rmax2 = fmaxf(rmax2, fmaxf(sc[nt][2], sc[nt][3]));
        }
        rmax1 = fmaxf(rmax1, __shfl_xor_sync(0xffffffffu, rmax1, 1, 4));
        rmax1 = fmaxf(rmax1, __shfl_xor_sync(0xffffffffu, rmax1, 2, 4));
        rmax2 = fmaxf(rmax2, __shfl_xor_sync(0xffffffffu, rmax2, 1, 4));
        rmax2 = fmaxf(rmax2, __shfl_xor_sync(0xffffffffu, rmax2, 2, 4));

        float mn1 = fmaxf(m1, rmax1), mn2 = fmaxf(m2, rmax2);
        float corr1 = ex2f(m1 - mn1), corr2 = ex2f(m2 - mn2);

        float sum1 = 0.f, sum2 = 0.f;
#pragma unroll
        for (int nt = 0; nt < 8; nt++) {
            float p0 = ex2f(sc[nt][0] - mn1);
            float p1 = ex2f(sc[nt][1] - mn1);
            float p2 = ex2f(sc[nt][2] - mn2);
            float p3 = ex2f(sc[nt][3] - mn2);
            sum1 += p0 + p1;
            sum2 += p2 + p3;
            *(float2*)&Qp[(wb + g) * FSTR + nt * 8 + 2 * l4] =
                make_float2(f2tf_f(p0), f2tf_f(p1));
            *(float2*)&Qp[(wb + g + 8) * FSTR + nt * 8 + 2 * l4] =
                make_float2(f2tf_f(p2), f2tf_f(p3));
        }
        sum1 += __shfl_xor_sync(0xffffffffu, sum1, 1, 4);
        sum1 += __shfl_xor_sync(0xffffffffu, sum1, 2, 4);
        sum2 += __shfl_xor_sync(0xffffffffu, sum2, 1, 4);
        sum2 += __shfl_xor_sync(0xffffffffu, sum2, 2, 4);

        l1 = l1 * corr1 + sum1;  m1 = mn1;
        l2 = l2 * corr2 + sum2;  m2 = mn2;
#pragma unroll
        for (int nt = 0; nt < 8; nt++) {
            oc[nt][0] *= corr1; oc[nt][1] *= corr1;
            oc[nt][2] *= corr2; oc[nt][3] *= corr2;
        }

        __syncwarp();   // P slab is warp-private (rows wb..wb+15)

        // ---- O += P @ V
#pragma unroll
        for (int k = 0; k < 8; k++) {
            int pa = (wb + g) * FSTR + k * 8 + l4;
            unsigned a0 = __float_as_uint(Qp[pa]);
            unsigned a1 = __float_as_uint(Qp[pa + 8 * FSTR]);
            unsigned a2 = __float_as_uint(Qp[pa + 4]);
            unsigned a3 = __float_as_uint(Qp[pa + 8 * FSTR + 4]);
#pragma unroll
            for (int nt = 0; nt < 8; nt++) {
                unsigned b0 = __float_as_uint(Vc[(k * 8 + l4) * FSTR + nt * 8 + g]);
                unsigned b1 = __float_as_uint(Vc[(k * 8 + l4 + 4) * FSTR + nt * 8 + g]);
                mma_tf32(oc[nt][0], oc[nt][1], oc[nt][2], oc[nt][3],
                         a0, a1, a2, a3, b0, b1);
            }
        }
        // no trailing __syncthreads: next iter's top sync protects buffer reuse
    }

    float inv1 = 1.0f / l1, inv2 = 1.0f / l2;
    float* Ob = g_attn + (size_t)n * TT * DD + (size_t)(qt * BQ) * DD + h * HDIM;
#pragma unroll
    for (int nt = 0; nt < 8; nt++) {
        *(float2*)&Ob[(size_t)(wb + g) * DD + nt * 8 + 2 * l4] =
            make_float2(oc[nt][0] * inv1, oc[nt][1] * inv1);
        *(float2*)&Ob[(size_t)(wb + g + 8) * DD + nt * 8 + 2 * l4] =
            make_float2(oc[nt][2] * inv2, oc[nt][3] * inv2);
    }
}

// ---------------------------------------------------------------------------
// Launch
// ---------------------------------------------------------------------------
extern "C" void kernel_launch(void* const* d_in, const int* in_sizes, int n_in,
                              void* d_out, int out_size) {
    const float* q  = (const float*)d_in[0];
    const float* Wk = (const float*)d_in[1];
    const float* Wv = (const float*)d_in[2];
    const float* Wo = (const float*)d_in[3];
    float* out = (float*)d_out;

    float *keys, *vals, *attn;
    cudaGetSymbolAddress((void**)&keys, g_keys);
    cudaGetSymbolAddress((void**)&vals, g_vals);
    cudaGetSymbolAddress((void**)&attn, g_attn);

    dim3 gGemm(MROWS / 128, DD / 128);   // (64, 4)

    // keys = tf32(q @ Wk^T + q) ; vals = tf32(q @ Wv^T)
    tgemm_nt<true , true ><<<gGemm, 256>>>(q, Wk, keys);
    tgemm_nt<false, true ><<<gGemm, 256>>>(q, Wv, vals);

    // flash attention on tensor cores (tf32, cp.async double-buffered)
    cudaFuncSetAttribute(flash_attn_tc, cudaFuncAttributeMaxDynamicSharedMemorySize,
                         FLASH_SMEM_BYTES);
    dim3 gFlash(TT / BQ, NB * HH);       // (16, 32)
    flash_attn_tc<<<gFlash, 256, FLASH_SMEM_BYTES>>>(q);

    // out = attn @ Wo^T   (fp32 output, no rounding)
    tgemm_nt<false, false><<<gGemm, 256>>>(attn, Wo, out);
}

// round 14
// speedup vs baseline: 1.2692x; 1.2168x over previous
#include <cuda_runtime.h>
#include <cstdint>

// Problem constants
#define NB 4
#define TT 2048
#define DD 512
#define HH 8
#define HDIM 64
#define MROWS (NB * TT)   // 8192

// Scratch (allocation-free: __device__ globals)
__device__ float g_keys[NB * TT * DD];   // [n][tok][h*64+d], tf32-RNE-rounded
__device__ float g_vals[NB * TT * DD];   // TRANSPOSED: [(n*512 + h*64 + d)][tok], tf32-rounded
__device__ float g_attn[NB * TT * DD];

// ---------------------------------------------------------------------------
// Helpers: tf32 cvt, ex2, mma.sync tf32, cp.async, ldmatrix.x4
// ---------------------------------------------------------------------------
__device__ __forceinline__ unsigned f2tf(float x) {
    unsigned r;
    asm("cvt.rna.tf32.f32 %0, %1;" : "=r"(r) : "f"(x));
    return r;
}
__device__ __forceinline__ float f2tf_f(float x) { return __uint_as_float(f2tf(x)); }

__device__ __forceinline__ float ex2f(float x) {
    float y;
    asm("ex2.approx.ftz.f32 %0, %1;" : "=f"(y) : "f"(x));
    return y;
}

__device__ __forceinline__ void mma_tf32(float& c0, float& c1, float& c2, float& c3,
                                         unsigned a0, unsigned a1, unsigned a2, unsigned a3,
                                         unsigned b0, unsigned b1) {
    asm volatile(
        "mma.sync.aligned.m16n8k8.row.col.f32.tf32.tf32.f32 "
        "{%0,%1,%2,%3}, {%4,%5,%6,%7}, {%8,%9}, {%0,%1,%2,%3};"
        : "+f"(c0), "+f"(c1), "+f"(c2), "+f"(c3)
        : "r"(a0), "r"(a1), "r"(a2), "r"(a3), "r"(b0), "r"(b1));
}

__device__ __forceinline__ void cp_async16(unsigned saddr, const void* gptr) {
    asm volatile("cp.async.cg.shared.global [%0], [%1], 16;" :: "r"(saddr), "l"(gptr));
}

__device__ __forceinline__ void ldsm_x4(unsigned& r0, unsigned& r1, unsigned& r2, unsigned& r3,
                                        uint32_t addr) {
    asm volatile("ldmatrix.sync.aligned.m8n8.x4.shared.b16 {%0,%1,%2,%3}, [%4];"
                 : "=r"(r0), "=r"(r1), "=r"(r2), "=r"(r3) : "r"(addr));
}

__device__ __forceinline__ uint32_t smem_u32(const void* p) {
    return (uint32_t)__cvta_generic_to_shared(p);
}

// ---------------------------------------------------------------------------
// Tensor-core GEMM NT (tf32 mma.sync): C = A @ B^T (+ residual A). Proven R8.
// TF32OUT: round stored result. TRANSP: scatter-store transposed vals layout
// C_t[(n*512 + col)][tok] (col = h*64+d, tok = row%2048).
// ---------------------------------------------------------------------------
#define GSTR 36

template <bool RESIDUAL, bool TF32OUT, bool TRANSP>
__global__ __launch_bounds__(256, 2) void tgemm_nt(const float* __restrict__ A,
                                                   const float* __restrict__ B,
                                                   float* __restrict__ C) {
    constexpr int BM = 128, BN = 128, BK = 32;
    __shared__ float Asm[BM * GSTR];
    __shared__ float Bsm[BN * GSTR];

    const int tid  = threadIdx.x;
    const int lane = tid & 31;
    const int wid  = tid >> 5;
    const int l4   = lane & 3;
    const int g    = lane >> 2;
    const int wm   = (wid & 3) * 32;
    const int wn   = (wid >> 2) * 64;
    const int bm   = blockIdx.x * BM;
    const int bn   = blockIdx.y * BN;

    float c[2][8][4];
#pragma unroll
    for (int mt = 0; mt < 2; mt++)
#pragma unroll
        for (int nt = 0; nt < 8; nt++)
#pragma unroll
            for (int j = 0; j < 4; j++) c[mt][nt][j] = 0.f;

    for (int k0 = 0; k0 < DD; k0 += BK) {
        __syncthreads();
#pragma unroll
        for (int it = 0; it < 4; it++) {
            int i  = tid + it * 256;
            int r  = i >> 3;
            int c4 = (i & 7) << 2;
            float4 va = *(const float4*)(A + (size_t)(bm + r) * DD + k0 + c4);
            *(float4*)&Asm[r * GSTR + c4] =
                make_float4(f2tf_f(va.x), f2tf_f(va.y), f2tf_f(va.z), f2tf_f(va.w));
            float4 vb = *(const float4*)(B + (size_t)(bn + r) * DD + k0 + c4);
            *(float4*)&Bsm[r * GSTR + c4] =
                make_float4(f2tf_f(vb.x), f2tf_f(vb.y), f2tf_f(vb.z), f2tf_f(vb.w));
        }
        __syncthreads();

#pragma unroll
        for (int k8 = 0; k8 < BK / 8; k8++) {
            unsigned a[2][4];
#pragma unroll
            for (int mt = 0; mt < 2; mt++) {
                int base = (wm + mt * 16 + g) * GSTR + k8 * 8 + l4;
                a[mt][0] = __float_as_uint(Asm[base]);
                a[mt][1] = __float_as_uint(Asm[base + 8 * GSTR]);
                a[mt][2] = __float_as_uint(Asm[base + 4]);
                a[mt][3] = __float_as_uint(Asm[base + 8 * GSTR + 4]);
            }
#pragma unroll
            for (int nt = 0; nt < 8; nt++) {
                int bb = (wn + nt * 8 + g) * GSTR + k8 * 8 + l4;
                unsigned b0 = __float_as_uint(Bsm[bb]);
                unsigned b1 = __float_as_uint(Bsm[bb + 4]);
                mma_tf32(c[0][nt][0], c[0][nt][1], c[0][nt][2], c[0][nt][3],
                         a[0][0], a[0][1], a[0][2], a[0][3], b0, b1);
                mma_tf32(c[1][nt][0], c[1][nt][1], c[1][nt][2], c[1][nt][3],
                         a[1][0], a[1][1], a[1][2], a[1][3], b0, b1);
            }
        }
    }

#pragma unroll
    for (int mt = 0; mt < 2; mt++) {
        int r1 = bm + wm + mt * 16 + g;
        int r2 = r1 + 8;
#pragma unroll
        for (int nt = 0; nt < 8; nt++) {
            int col = bn + wn + nt * 8 + 2 * l4;
            float2 v1 = make_float2(c[mt][nt][0], c[mt][nt][1]);
            float2 v2 = make_float2(c[mt][nt][2], c[mt][nt][3]);
            if (RESIDUAL) {
                float2 q1 = *(const float2*)(A + (size_t)r1 * DD + col);
                float2 q2 = *(const float2*)(A + (size_t)r2 * DD + col);
                v1.x += q1.x; v1.y += q1.y;
                v2.x += q2.x; v2.y += q2.y;
            }
            if (TF32OUT) {
                v1.x = f2tf_f(v1.x); v1.y = f2tf_f(v1.y);
                v2.x = f2tf_f(v2.x); v2.y = f2tf_f(v2.y);
            }
            if (TRANSP) {
                // C_t[(n*512 + col)][tok]: n = row>>11, tok = row&2047
                size_t b1a = ((size_t)(r1 >> 11) * 512 + col) * TT + (r1 & 2047);
                size_t b2a = ((size_t)(r2 >> 11) * 512 + col) * TT + (r2 & 2047);
                C[b1a]      = v1.x;
                C[b1a + TT] = v1.y;   // col+1 -> +TT in transposed layout
                C[b2a]      = v2.x;
                C[b2a + TT] = v2.y;
            } else {
                *(float2*)(C + (size_t)r1 * DD + col) = v1;
                *(float2*)(C + (size_t)r2 * DD + col) = v2;
            }
        }
    }
}

// ---------------------------------------------------------------------------
// Flash attention, tf32 mma.sync + ldmatrix fragment loads.
// K smem [tok][d]; V smem TRANSPOSED [d][tok] (from transposed gmem vals);
// P slab [row][tok]. All fragment loads via ldmatrix.m8n8.x4.b16.
// ---------------------------------------------------------------------------
#define BQ 128
#define BKV 64
#define FSTR 68
#define NKT (TT / BKV)   // 32 KV tiles

#define FLASH_SMEM_FLOATS (FSTR * (BQ + 4 * BKV))
#define FLASH_SMEM_BYTES (FLASH_SMEM_FLOATS * 4)

__global__ __launch_bounds__(256, 2) void flash_attn_tc(const float* __restrict__ Q) {
    extern __shared__ float sm[];
    float* Qp  = sm;                      // Q staging, then P slab (warp-private rows)
    float* Ks0 = Qp  + BQ  * FSTR;
    float* Ks1 = Ks0 + BKV * FSTR;
    float* Vs0 = Ks1 + BKV * FSTR;        // [d][tok]
    float* Vs1 = Vs0 + BKV * FSTR;

    const unsigned ks0u = smem_u32(Ks0);
    const unsigned ks1u = smem_u32(Ks1);
    const unsigned vs0u = smem_u32(Vs0);
    const unsigned vs1u = smem_u32(Vs1);
    const unsigned qpu  = smem_u32(Qp);

    const int tid  = threadIdx.x;
    const int lane = tid & 31;
    const int wid  = tid >> 5;
    const int l4   = lane & 3;
    const int g    = lane >> 2;
    const int wb   = wid * 16;

    const int qt = blockIdx.x;
    const int nh = blockIdx.y;
    const int n  = nh >> 3;
    const int h  = nh & 7;

    const float* Qbase = Q      + (size_t)n * TT * DD + (size_t)(qt * BQ) * DD + h * HDIM;
    const float* Kbase = g_keys + (size_t)n * TT * DD + h * HDIM;
    const float* Vtb   = g_vals + ((size_t)n * 512 + h * HDIM) * TT;   // [64 d][2048 tok]

    // ldmatrix per-lane offsets (bytes).
    // K/V matrices (per j, per k): mat m = lane>>3; nt = 2j + (m>>1); h4 = m&1;
    //   fragment b_{h4}[nt] row = lane&7.
    const int mrow = lane & 7;
    const int mh   = lane >> 3;          // 0..3
    unsigned kvoff[4];
#pragma unroll
    for (int j = 0; j < 4; j++)
        kvoff[j] = (unsigned)((((2 * j + (mh >> 1)) * 8 + mrow) * FSTR + 4 * (mh & 1)) * 4);
    // P matrices: a0..a3 -> row_off = (m&1)*8, col_off = (m>>1)*4
    const unsigned poff =
        (unsigned)(((wb + mrow + (mh & 1) * 8) * FSTR + 4 * (mh >> 1)) * 4);

    // Q tile staging: pre-scale by (1/sqrt(HD)) * log2(e).
    const float QSCALE = 0.125f * 1.44269504088896341f;
    for (int i = tid; i < BQ * 16; i += 256) {
        int r = i >> 4, d4 = (i & 15) << 2;
        float4 v = *(const float4*)(Qbase + (size_t)r * DD + d4);
        *(float4*)&Qp[r * FSTR + d4] =
            make_float4(f2tf_f(v.x * QSCALE), f2tf_f(v.y * QSCALE),
                        f2tf_f(v.z * QSCALE), f2tf_f(v.w * QSCALE));
    }

    // Prologue: async-load KV tile 0 (K [tok][d]; V transposed [d][tok]).
#pragma unroll
    for (int it = 0; it < 4; it++) {
        int i = tid + it * 256;
        int r = i >> 4, c4 = (i & 15) << 2;
        unsigned off = (unsigned)(r * FSTR + c4) * 4u;
        cp_async16(ks0u + off, Kbase + (size_t)r * DD + c4);          // r=tok, c4=d
        cp_async16(vs0u + off, Vtb + (size_t)r * TT + c4);            // r=d, c4=tok
    }
    asm volatile("cp.async.commit_group;");

    __syncthreads();   // Qp staging complete

    // Hoist Q fragments (loop-invariant) via ldmatrix (one x4 per kstep).
    unsigned qf[8][4];
#pragma unroll
    for (int k = 0; k < 8; k++)
        ldsm_x4(qf[k][0], qf[k][1], qf[k][2], qf[k][3], qpu + poff + k * 32);

    float m1 = -1e30f, m2 = -1e30f, l1 = 0.f, l2 = 0.f;
    float oc[8][4];
#pragma unroll
    for (int nt = 0; nt < 8; nt++)
#pragma unroll
        for (int j = 0; j < 4; j++) oc[nt][j] = 0.f;

    for (int kt = 0; kt < NKT; kt++) {
        const bool odd = kt & 1;
        const unsigned kc = odd ? ks1u : ks0u;
        const unsigned vc = odd ? vs1u : vs0u;

        asm volatile("cp.async.wait_group 0;");
        __syncthreads();   // publishes tile kt; proves other buffer consumed

        if (kt + 1 < NKT) {
            unsigned knu = odd ? ks0u : ks1u;
            unsigned vnu = odd ? vs0u : vs1u;
            const float* Kt = Kbase + (size_t)((kt + 1) * BKV) * DD;
            const float* Vt = Vtb + (kt + 1) * BKV;
#pragma unroll
            for (int it = 0; it < 4; it++) {
                int i = tid + it * 256;
                int r = i >> 4, c4 = (i & 15) << 2;
                unsigned off = (unsigned)(r * FSTR + c4) * 4u;
                cp_async16(knu + off, Kt + (size_t)r * DD + c4);
                cp_async16(vnu + off, Vt + (size_t)r * TT + c4);
            }
            asm volatile("cp.async.commit_group;");
        }

        // ---- S = Q @ K^T  (ldmatrix K fragments: 4 x4-instrs per kstep)
        float sc[8][4];
#pragma unroll
        for (int nt = 0; nt < 8; nt++)
#pragma unroll
            for (int j = 0; j < 4; j++) sc[nt][j] = 0.f;

#pragma unroll
        for (int k = 0; k < 8; k++) {
            unsigned kb0[8], kb1[8];
#pragma unroll
            for (int j = 0; j < 4; j++)
                ldsm_x4(kb0[2 * j], kb1[2 * j], kb0[2 * j + 1], kb1[2 * j + 1],
                        kc + kvoff[j] + k * 32);
#pragma unroll
            for (int nt = 0; nt < 8; nt++)
                mma_tf32(sc[nt][0], sc[nt][1], sc[nt][2], sc[nt][3],
                         qf[k][0], qf[k][1], qf[k][2], qf[k][3], kb0[nt], kb1[nt]);
        }

        // ---- Online softmax (exp2 domain, MUFU)
        float rmax1 = -1e30f, rmax2 = -1e30f;
#pragma unroll
        for (int nt = 0; nt < 8; nt++) {
            rmax1 = fmaxf(rmax1, fmaxf(sc[nt][0], sc[nt][1]));
            rmax2 = fmaxf(rmax2, fmaxf(sc[nt][2], sc[nt][3]));
        }
        rmax1 = fmaxf(rmax1, __shfl_xor_sync(0xffffffffu, rmax1, 1, 4));
        rmax1 = fmaxf(rmax1, __shfl_xor_sync(0xffffffffu, rmax1, 2, 4));
        rmax2 = fmaxf(rmax2, __shfl_xor_sync(0xffffffffu, rmax2, 1, 4));
        rmax2 = fmaxf(rmax2, __shfl_xor_sync(0xffffffffu, rmax2, 2, 4));

        float mn1 = fmaxf(m1, rmax1), mn2 = fmaxf(m2, rmax2);
        float corr1 = ex2f(m1 - mn1), corr2 = ex2f(m2 - mn2);

        float sum1 = 0.f, sum2 = 0.f;
#pragma unroll
        for (int nt = 0; nt < 8; nt++) {
            float p0 = ex2f(sc[nt][0] - mn1);
            float p1 = ex2f(sc[nt][1] - mn1);
            float p2 = ex2f(sc[nt][2] - mn2);
            float p3 = ex2f(sc[nt][3] - mn2);
            sum1 += p0 + p1;
            sum2 += p2 + p3;
            *(float2*)&Qp[(wb + g) * FSTR + nt * 8 + 2 * l4] =
                make_float2(f2tf_f(p0), f2tf_f(p1));
            *(float2*)&Qp[(wb + g + 8) * FSTR + nt * 8 + 2 * l4] =
                make_float2(f2tf_f(p2), f2tf_f(p3));
        }
        sum1 += __shfl_xor_sync(0xffffffffu, sum1, 1, 4);
        sum1 += __shfl_xor_sync(0xffffffffu, sum1, 2, 4);
        sum2 += __shfl_xor_sync(0xffffffffu, sum2, 1, 4);
        sum2 += __shfl_xor_sync(0xffffffffu, sum2, 2, 4);

        l1 = l1 * corr1 + sum1;  m1 = mn1;
        l2 = l2 * corr2 + sum2;  m2 = mn2;
#pragma unroll
        for (int nt = 0; nt < 8; nt++) {
            oc[nt][0] *= corr1; oc[nt][1] *= corr1;
            oc[nt][2] *= corr2; oc[nt][3] *= corr2;
        }

        __syncwarp();   // P slab is warp-private (rows wb..wb+15)

        // ---- O += P @ V  (ldmatrix P + transposed-V fragments)
#pragma unroll
        for (int k = 0; k < 8; k++) {
            unsigned pa[4];
            ldsm_x4(pa[0], pa[1], pa[2], pa[3], qpu + poff + k * 32);
            unsigned vb0[8], vb1[8];
#pragma unroll
            for (int j = 0; j < 4; j++)
                ldsm_x4(vb0[2 * j], vb1[2 * j], vb0[2 * j + 1], vb1[2 * j + 1],
                        vc + kvoff[j] + k * 32);
#pragma unroll
            for (int nt = 0; nt < 8; nt++)
                mma_tf32(oc[nt][0], oc[nt][1], oc[nt][2], oc[nt][3],
                         pa[0], pa[1], pa[2], pa[3], vb0[nt], vb1[nt]);
        }
        // no trailing __syncthreads: next iter's top sync protects buffer reuse
    }

    float inv1 = 1.0f / l1, inv2 = 1.0f / l2;
    float* Ob = g_attn + (size_t)n * TT * DD + (size_t)(qt * BQ) * DD + h * HDIM;
#pragma unroll
    for (int nt = 0; nt < 8; nt++) {
        *(float2*)&Ob[(size_t)(wb + g) * DD + nt * 8 + 2 * l4] =
            make_float2(oc[nt][0] * inv1, oc[nt][1] * inv1);
        *(float2*)&Ob[(size_t)(wb + g + 8) * DD + nt * 8 + 2 * l4] =
            make_float2(oc[nt][2] * inv2, oc[nt][3] * inv2);
    }
}

// ---------------------------------------------------------------------------
// Launch
// ---------------------------------------------------------------------------
extern "C" void kernel_launch(void* const* d_in, const int* in_sizes, int n_in,
                              void* d_out, int out_size) {
    const float* q  = (const float*)d_in[0];
    const float* Wk = (const float*)d_in[1];
    const float* Wv = (const float*)d_in[2];
    const float* Wo = (const float*)d_in[3];
    float* out = (float*)d_out;

    float *keys, *vals, *attn;
    cudaGetSymbolAddress((void**)&keys, g_keys);
    cudaGetSymbolAddress((void**)&vals, g_vals);
    cudaGetSymbolAddress((void**)&attn, g_attn);

    dim3 gGemm(MROWS / 128, DD / 128);   // (64, 4)

    // keys = tf32(q @ Wk^T + q) ; vals = tf32(q @ Wv^T) stored TRANSPOSED
    tgemm_nt<true , true , false><<<gGemm, 256>>>(q, Wk, keys);
    tgemm_nt<false, true , true ><<<gGemm, 256>>>(q, Wv, vals);

    // flash attention (tf32 mma.sync + ldmatrix, cp.async double-buffered)
    cudaFuncSetAttribute(flash_attn_tc, cudaFuncAttributeMaxDynamicSharedMemorySize,
                         FLASH_SMEM_BYTES);
    dim3 gFlash(TT / BQ, NB * HH);       // (16, 32)
    flash_attn_tc<<<gFlash, 256, FLASH_SMEM_BYTES>>>(q);

    // out = attn @ Wo^T   (fp32 output)
    tgemm_nt<false, false, false><<<gGemm, 256>>>(attn, Wo, out);
}

// round 15
// speedup vs baseline: 1.3051x; 1.0283x over previous
#include <cuda_runtime.h>
#include <cstdint>

// Problem constants
#define NB 4
#define TT 2048
#define DD 512
#define HH 8
#define HDIM 64
#define MROWS (NB * TT)   // 8192

// Scratch (allocation-free: __device__ globals)
__device__ float g_keys[NB * TT * DD];   // [n][tok][h*64+d], tf32-RNE-rounded
__device__ float g_vals[NB * TT * DD];   // TRANSPOSED: [(n*512 + h*64 + d)][tok], tf32-rounded
__device__ float g_attn[NB * TT * DD];

// ---------------------------------------------------------------------------
// Helpers: tf32 cvt, ex2, mma.sync tf32, cp.async, ldmatrix.x4
// ---------------------------------------------------------------------------
__device__ __forceinline__ unsigned f2tf(float x) {
    unsigned r;
    asm("cvt.rna.tf32.f32 %0, %1;" : "=r"(r) : "f"(x));
    return r;
}
__device__ __forceinline__ float f2tf_f(float x) { return __uint_as_float(f2tf(x)); }

__device__ __forceinline__ float ex2f(float x) {
    float y;
    asm("ex2.approx.ftz.f32 %0, %1;" : "=f"(y) : "f"(x));
    return y;
}

__device__ __forceinline__ void mma_tf32(float& c0, float& c1, float& c2, float& c3,
                                         unsigned a0, unsigned a1, unsigned a2, unsigned a3,
                                         unsigned b0, unsigned b1) {
    asm volatile(
        "mma.sync.aligned.m16n8k8.row.col.f32.tf32.tf32.f32 "
        "{%0,%1,%2,%3}, {%4,%5,%6,%7}, {%8,%9}, {%0,%1,%2,%3};"
        : "+f"(c0), "+f"(c1), "+f"(c2), "+f"(c3)
        : "r"(a0), "r"(a1), "r"(a2), "r"(a3), "r"(b0), "r"(b1));
}

__device__ __forceinline__ void cp_async16(unsigned saddr, const void* gptr) {
    asm volatile("cp.async.cg.shared.global [%0], [%1], 16;" :: "r"(saddr), "l"(gptr));
}

__device__ __forceinline__ void ldsm_x4(unsigned& r0, unsigned& r1, unsigned& r2, unsigned& r3,
                                        uint32_t addr) {
    asm volatile("ldmatrix.sync.aligned.m8n8.x4.shared.b16 {%0,%1,%2,%3}, [%4];"
                 : "=r"(r0), "=r"(r1), "=r"(r2), "=r"(r3) : "r"(addr));
}

__device__ __forceinline__ uint32_t smem_u32(const void* p) {
    return (uint32_t)__cvta_generic_to_shared(p);
}

// ---------------------------------------------------------------------------
// Tensor-core GEMM NT (tf32 mma.sync + ldmatrix fragments): C = A @ B^T
// (+ residual A). BM=BN=128, BK=32, 8 warps (4M x 2N), warp tile 32x64.
// TF32OUT: round stored result. TRANSP: scatter transposed vals layout.
// ---------------------------------------------------------------------------
#define GSTR 36

template <bool RESIDUAL, bool TF32OUT, bool TRANSP>
__global__ __launch_bounds__(256, 2) void tgemm_nt(const float* __restrict__ A,
                                                   const float* __restrict__ B,
                                                   float* __restrict__ C) {
    constexpr int BM = 128, BN = 128, BK = 32;
    __shared__ float Asm[BM * GSTR];
    __shared__ float Bsm[BN * GSTR];

    const int tid  = threadIdx.x;
    const int lane = tid & 31;
    const int wid  = tid >> 5;
    const int l4   = lane & 3;
    const int g    = lane >> 2;
    const int wm   = (wid & 3) * 32;
    const int wn   = (wid >> 2) * 64;
    const int bm   = blockIdx.x * BM;
    const int bn   = blockIdx.y * BN;

    // ldmatrix lane-address components (same proven mappings as flash R14).
    const int mrow = lane & 7;
    const int mh   = lane >> 3;          // matrix index 0..3
    const uint32_t asmu = smem_u32(Asm);
    const uint32_t bsmu = smem_u32(Bsm);
    // A (per mt): m0=a0(row,0) m1=a1(row+8,0) m2=a2(row,4) m3=a3(row+8,4)
    uint32_t aoff[2];
#pragma unroll
    for (int mt = 0; mt < 2; mt++)
        aoff[mt] = asmu +
            (uint32_t)(((wm + mt * 16 + mrow + (mh & 1) * 8) * GSTR + 4 * (mh >> 1)) * 4);
    // B (per j): m0=b0[2j] m1=b1[2j] m2=b0[2j+1] m3=b1[2j+1]
    uint32_t boff[4];
#pragma unroll
    for (int j = 0; j < 4; j++)
        boff[j] = bsmu +
            (uint32_t)(((wn + (2 * j + (mh >> 1)) * 8 + mrow) * GSTR + 4 * (mh & 1)) * 4);

    float c[2][8][4];
#pragma unroll
    for (int mt = 0; mt < 2; mt++)
#pragma unroll
        for (int nt = 0; nt < 8; nt++)
#pragma unroll
            for (int j = 0; j < 4; j++) c[mt][nt][j] = 0.f;

    for (int k0 = 0; k0 < DD; k0 += BK) {
        __syncthreads();
#pragma unroll
        for (int it = 0; it < 4; it++) {
            int i  = tid + it * 256;
            int r  = i >> 3;
            int c4 = (i & 7) << 2;
            float4 va = *(const float4*)(A + (size_t)(bm + r) * DD + k0 + c4);
            *(float4*)&Asm[r * GSTR + c4] =
                make_float4(f2tf_f(va.x), f2tf_f(va.y), f2tf_f(va.z), f2tf_f(va.w));
            float4 vb = *(const float4*)(B + (size_t)(bn + r) * DD + k0 + c4);
            *(float4*)&Bsm[r * GSTR + c4] =
                make_float4(f2tf_f(vb.x), f2tf_f(vb.y), f2tf_f(vb.z), f2tf_f(vb.w));
        }
        __syncthreads();

#pragma unroll
        for (int k8 = 0; k8 < BK / 8; k8++) {
            unsigned a[2][4];
#pragma unroll
            for (int mt = 0; mt < 2; mt++)
                ldsm_x4(a[mt][0], a[mt][1], a[mt][2], a[mt][3], aoff[mt] + k8 * 32);
            unsigned b0[8], b1[8];
#pragma unroll
            for (int j = 0; j < 4; j++)
                ldsm_x4(b0[2 * j], b1[2 * j], b0[2 * j + 1], b1[2 * j + 1],
                        boff[j] + k8 * 32);
#pragma unroll
            for (int nt = 0; nt < 8; nt++) {
                mma_tf32(c[0][nt][0], c[0][nt][1], c[0][nt][2], c[0][nt][3],
                         a[0][0], a[0][1], a[0][2], a[0][3], b0[nt], b1[nt]);
                mma_tf32(c[1][nt][0], c[1][nt][1], c[1][nt][2], c[1][nt][3],
                         a[1][0], a[1][1], a[1][2], a[1][3], b0[nt], b1[nt]);
            }
        }
    }

#pragma unroll
    for (int mt = 0; mt < 2; mt++) {
        int r1 = bm + wm + mt * 16 + g;
        int r2 = r1 + 8;
#pragma unroll
        for (int nt = 0; nt < 8; nt++) {
            int col = bn + wn + nt * 8 + 2 * l4;
            float2 v1 = make_float2(c[mt][nt][0], c[mt][nt][1]);
            float2 v2 = make_float2(c[mt][nt][2], c[mt][nt][3]);
            if (RESIDUAL) {
                float2 q1 = *(const float2*)(A + (size_t)r1 * DD + col);
                float2 q2 = *(const float2*)(A + (size_t)r2 * DD + col);
                v1.x += q1.x; v1.y += q1.y;
                v2.x += q2.x; v2.y += q2.y;
            }
            if (TF32OUT) {
                v1.x = f2tf_f(v1.x); v1.y = f2tf_f(v1.y);
                v2.x = f2tf_f(v2.x); v2.y = f2tf_f(v2.y);
            }
            if (TRANSP) {
                // C_t[(n*512 + col)][tok]: n = row>>11, tok = row&2047
                size_t b1a = ((size_t)(r1 >> 11) * 512 + col) * TT + (r1 & 2047);
                size_t b2a = ((size_t)(r2 >> 11) * 512 + col) * TT + (r2 & 2047);
                C[b1a]      = v1.x;
                C[b1a + TT] = v1.y;
                C[b2a]      = v2.x;
                C[b2a + TT] = v2.y;
            } else {
                *(float2*)(C + (size_t)r1 * DD + col) = v1;
                *(float2*)(C + (size_t)r2 * DD + col) = v2;
            }
        }
    }
}

// ---------------------------------------------------------------------------
// Flash attention, tf32 mma.sync + ldmatrix fragment loads. Proven R14.
// K smem [tok][d]; V smem TRANSPOSED [d][tok]; P slab [row][tok].
// ---------------------------------------------------------------------------
#define BQ 128
#define BKV 64
#define FSTR 68
#define NKT (TT / BKV)   // 32 KV tiles

#define FLASH_SMEM_FLOATS (FSTR * (BQ + 4 * BKV))
#define FLASH_SMEM_BYTES (FLASH_SMEM_FLOATS * 4)

__global__ __launch_bounds__(256, 2) void flash_attn_tc(const float* __restrict__ Q) {
    extern __shared__ float sm[];
    float* Qp  = sm;                      // Q staging, then P slab (warp-private rows)
    float* Ks0 = Qp  + BQ  * FSTR;
    float* Ks1 = Ks0 + BKV * FSTR;
    float* Vs0 = Ks1 + BKV * FSTR;        // [d][tok]
    float* Vs1 = Vs0 + BKV * FSTR;

    const unsigned ks0u = smem_u32(Ks0);
    const unsigned ks1u = smem_u32(Ks1);
    const unsigned vs0u = smem_u32(Vs0);
    const unsigned vs1u = smem_u32(Vs1);
    const unsigned qpu  = smem_u32(Qp);

    const int tid  = threadIdx.x;
    const int lane = tid & 31;
    const int wid  = tid >> 5;
    const int l4   = lane & 3;
    const int g    = lane >> 2;
    const int wb   = wid * 16;

    const int qt = blockIdx.x;
    const int nh = blockIdx.y;
    const int n  = nh >> 3;
    const int h  = nh & 7;

    const float* Qbase = Q      + (size_t)n * TT * DD + (size_t)(qt * BQ) * DD + h * HDIM;
    const float* Kbase = g_keys + (size_t)n * TT * DD + h * HDIM;
    const float* Vtb   = g_vals + ((size_t)n * 512 + h * HDIM) * TT;   // [64 d][2048 tok]

    const int mrow = lane & 7;
    const int mh   = lane >> 3;
    unsigned kvoff[4];
#pragma unroll
    for (int j = 0; j < 4; j++)
        kvoff[j] = (unsigned)((((2 * j + (mh >> 1)) * 8 + mrow) * FSTR + 4 * (mh & 1)) * 4);
    const unsigned poff =
        (unsigned)(((wb + mrow + (mh & 1) * 8) * FSTR + 4 * (mh >> 1)) * 4);

    const float QSCALE = 0.125f * 1.44269504088896341f;
    for (int i = tid; i < BQ * 16; i += 256) {
        int r = i >> 4, d4 = (i & 15) << 2;
        float4 v = *(const float4*)(Qbase + (size_t)r * DD + d4);
        *(float4*)&Qp[r * FSTR + d4] =
            make_float4(f2tf_f(v.x * QSCALE), f2tf_f(v.y * QSCALE),
                        f2tf_f(v.z * QSCALE), f2tf_f(v.w * QSCALE));
    }

#pragma unroll
    for (int it = 0; it < 4; it++) {
        int i = tid + it * 256;
        int r = i >> 4, c4 = (i & 15) << 2;
        unsigned off = (unsigned)(r * FSTR + c4) * 4u;
        cp_async16(ks0u + off, Kbase + (size_t)r * DD + c4);
        cp_async16(vs0u + off, Vtb + (size_t)r * TT + c4);
    }
    asm volatile("cp.async.commit_group;");

    __syncthreads();

    unsigned qf[8][4];
#pragma unroll
    for (int k = 0; k < 8; k++)
        ldsm_x4(qf[k][0], qf[k][1], qf[k][2], qf[k][3], qpu + poff + k * 32);

    float m1 = -1e30f, m2 = -1e30f, l1 = 0.f, l2 = 0.f;
    float oc[8][4];
#pragma unroll
    for (int nt = 0; nt < 8; nt++)
#pragma unroll
        for (int j = 0; j < 4; j++) oc[nt][j] = 0.f;

    for (int kt = 0; kt < NKT; kt++) {
        const bool odd = kt & 1;
        const unsigned kc = odd ? ks1u : ks0u;
        const unsigned vc = odd ? vs1u : vs0u;

        asm volatile("cp.async.wait_group 0;");
        __syncthreads();

        if (kt + 1 < NKT) {
            unsigned knu = odd ? ks0u : ks1u;
            unsigned vnu = odd ? vs0u : vs1u;
            const float* Kt = Kbase + (size_t)((kt + 1) * BKV) * DD;
            const float* Vt = Vtb + (kt + 1) * BKV;
#pragma unroll
            for (int it = 0; it < 4; it++) {
                int i = tid + it * 256;
                int r = i >> 4, c4 = (i & 15) << 2;
                unsigned off = (unsigned)(r * FSTR + c4) * 4u;
                cp_async16(knu + off, Kt + (size_t)r * DD + c4);
                cp_async16(vnu + off, Vt + (size_t)r * TT + c4);
            }
            asm volatile("cp.async.commit_group;");
        }

        float sc[8][4];
#pragma unroll
        for (int nt = 0; nt < 8; nt++)
#pragma unroll
            for (int j = 0; j < 4; j++) sc[nt][j] = 0.f;

#pragma unroll
        for (int k = 0; k < 8; k++) {
            unsigned kb0[8], kb1[8];
#pragma unroll
            for (int j = 0; j < 4; j++)
                ldsm_x4(kb0[2 * j], kb1[2 * j], kb0[2 * j + 1], kb1[2 * j + 1],
                        kc + kvoff[j] + k * 32);
#pragma unroll
            for (int nt = 0; nt < 8; nt++)
                mma_tf32(sc[nt][0], sc[nt][1], sc[nt][2], sc[nt][3],
                         qf[k][0], qf[k][1], qf[k][2], qf[k][3], kb0[nt], kb1[nt]);
        }

        float rmax1 = -1e30f, rmax2 = -1e30f;
#pragma unroll
        for (int nt = 0; nt < 8; nt++) {
            rmax1 = fmaxf(rmax1, fmaxf(sc[nt][0], sc[nt][1]));
            rmax2 = fmaxf(rmax2, fmaxf(sc[nt][2], sc[nt][3]));
        }
        rmax1 = fmaxf(rmax1, __shfl_xor_sync(0xffffffffu, rmax1, 1, 4));
        rmax1 = fmaxf(rmax1, __shfl_xor_sync(0xffffffffu, rmax1, 2, 4));
        rmax2 = fmaxf(rmax2, __shfl_xor_sync(0xffffffffu, rmax2, 1, 4));
        rmax2 = fmaxf(rmax2, __shfl_xor_sync(0xffffffffu, rmax2, 2, 4));

        float mn1 = fmaxf(m1, rmax1), mn2 = fmaxf(m2, rmax2);
        float corr1 = ex2f(m1 - mn1), corr2 = ex2f(m2 - mn2);

        float sum1 = 0.f, sum2 = 0.f;
#pragma unroll
        for (int nt = 0; nt < 8; nt++) {
            float p0 = ex2f(sc[nt][0] - mn1);
            float p1 = ex2f(sc[nt][1] - mn1);
            float p2 = ex2f(sc[nt][2] - mn2);
            float p3 = ex2f(sc[nt][3] - mn2);
            sum1 += p0 + p1;
            sum2 += p2 + p3;
            *(float2*)&Qp[(wb + g) * FSTR + nt * 8 + 2 * l4] =
                make_float2(f2tf_f(p0), f2tf_f(p1));
            *(float2*)&Qp[(wb + g + 8) * FSTR + nt * 8 + 2 * l4] =
                make_float2(f2tf_f(p2), f2tf_f(p3));
        }
        sum1 += __shfl_xor_sync(0xffffffffu, sum1, 1, 4);
        sum1 += __shfl_xor_sync(0xffffffffu, sum1, 2, 4);
        sum2 += __shfl_xor_sync(0xffffffffu, sum2, 1, 4);
        sum2 += __shfl_xor_sync(0xffffffffu, sum2, 2, 4);

        l1 = l1 * corr1 + sum1;  m1 = mn1;
        l2 = l2 * corr2 + sum2;  m2 = mn2;
#pragma unroll
        for (int nt = 0; nt < 8; nt++) {
            oc[nt][0] *= corr1; oc[nt][1] *= corr1;
            oc[nt][2] *= corr2; oc[nt][3] *= corr2;
        }

        __syncwarp();

#pragma unroll
        for (int k = 0; k < 8; k++) {
            unsigned pa[4];
            ldsm_x4(pa[0], pa[1], pa[2], pa[3], qpu + poff + k * 32);
            unsigned vb0[8], vb1[8];
#pragma unroll
            for (int j = 0; j < 4; j++)
                ldsm_x4(vb0[2 * j], vb1[2 * j], vb0[2 * j + 1], vb1[2 * j + 1],
                        vc + kvoff[j] + k * 32);
#pragma unroll
            for (int nt = 0; nt < 8; nt++)
                mma_tf32(oc[nt][0], oc[nt][1], oc[nt][2], oc[nt][3],
                         pa[0], pa[1], pa[2], pa[3], vb0[nt], vb1[nt]);
        }
    }

    float inv1 = 1.0f / l1, inv2 = 1.0f / l2;
    float* Ob = g_attn + (size_t)n * TT * DD + (size_t)(qt * BQ) * DD + h * HDIM;
#pragma unroll
    for (int nt = 0; nt < 8; nt++) {
        *(float2*)&Ob[(size_t)(wb + g) * DD + nt * 8 + 2 * l4] =
            make_float2(oc[nt][0] * inv1, oc[nt][1] * inv1);
        *(float2*)&Ob[(size_t)(wb + g + 8) * DD + nt * 8 + 2 * l4] =
            make_float2(oc[nt][2] * inv2, oc[nt][3] * inv2);
    }
}

// ---------------------------------------------------------------------------
// Launch
// ---------------------------------------------------------------------------
extern "C" void kernel_launch(void* const* d_in, const int* in_sizes, int n_in,
                              void* d_out, int out_size) {
    const float* q  = (const float*)d_in[0];
    const float* Wk = (const float*)d_in[1];
    const float* Wv = (const float*)d_in[2];
    const float* Wo = (const float*)d_in[3];
    float* out = (float*)d_out;

    float *keys, *vals, *attn;
    cudaGetSymbolAddress((void**)&keys, g_keys);
    cudaGetSymbolAddress((void**)&vals, g_vals);
    cudaGetSymbolAddress((void**)&attn, g_attn);

    dim3 gGemm(MROWS / 128, DD / 128);   // (64, 4)

    // keys = tf32(q @ Wk^T + q) ; vals = tf32(q @ Wv^T) stored TRANSPOSED
    tgemm_nt<true , true , false><<<gGemm, 256>>>(q, Wk, keys);
    tgemm_nt<false, true , true ><<<gGemm, 256>>>(q, Wv, vals);

    // flash attention (tf32 mma.sync + ldmatrix, cp.async double-buffered)
    cudaFuncSetAttribute(flash_attn_tc, cudaFuncAttributeMaxDynamicSharedMemorySize,
                         FLASH_SMEM_BYTES);
    dim3 gFlash(TT / BQ, NB * HH);       // (16, 32)
    flash_attn_tc<<<gFlash, 256, FLASH_SMEM_BYTES>>>(q);

    // out = attn @ Wo^T   (fp32 output)
    tgemm_nt<false, false, false><<<gGemm, 256>>>(attn, Wo, out);
}